// round 11
// baseline (speedup 1.0000x reference)
#include <cuda_runtime.h>
#include <cuda_bf16.h>
#include <cstdint>
#include <cstddef>

#define Bn   64
#define Tn   1024
#define Dn   512
#define Hn   256
#define Gn   1024     /* 4*H */
#define NTOT 2048     /* both directions */
#define Mrows (Bn * Tn)
#define EPSC 0.001f

// ---------------- scratch (static device globals; allocation-free) ----------------
__device__ float          g_xg[(size_t)Bn * Tn * NTOT];   // 512 MB  xg for both dirs
__device__ __nv_bfloat16  g_ahi[(size_t)Mrows * Dn];      // 64 MB
__device__ __nv_bfloat16  g_alo[(size_t)Mrows * Dn];      // 64 MB
__device__ __nv_bfloat16  g_wthi[(size_t)NTOT * Dn];      // 2 MB  W^T hi  [n][k]
__device__ __nv_bfloat16  g_wtlo[(size_t)NTOT * Dn];      // 2 MB  W^T lo
__device__ float          g_bias2[NTOT];
__device__ float          g_hbuf[2][2][Bn * Hn];          // [parity][dir][b*H+j]
__device__ int            g_len[Bn];
__device__ unsigned       g_flags[128];                   // [dir*64 + bs*8 + hs]

__device__ __forceinline__ float sigf(float x)  { return 1.0f / (1.0f + __expf(-x)); }
__device__ __forceinline__ float tanhf_(float x){ return 2.0f / (1.0f + __expf(-2.0f * x)) - 1.0f; }

__device__ __forceinline__ uint32_t smem_u32(const void* p) {
    uint32_t a;
    asm("{ .reg .u64 t; cvta.to.shared.u64 t, %1; cvt.u32.u64 %0, t; }" : "=r"(a) : "l"(p));
    return a;
}
__device__ __forceinline__ void cp16(uint32_t dst, const void* src) {
    asm volatile("cp.async.cg.shared.global [%0], [%1], 16;" :: "r"(dst), "l"(src));
}
#define CP_COMMIT() asm volatile("cp.async.commit_group;" ::: "memory")
#define CP_WAIT1()  asm volatile("cp.async.wait_group 1;" ::: "memory")
#define CP_WAIT0()  asm volatile("cp.async.wait_group 0;" ::: "memory")

__device__ __forceinline__ void ldsm4(uint32_t& r0, uint32_t& r1, uint32_t& r2, uint32_t& r3,
                                      uint32_t addr) {
    asm volatile("ldmatrix.sync.aligned.m8n8.x4.shared.b16 {%0,%1,%2,%3}, [%4];"
                 : "=r"(r0), "=r"(r1), "=r"(r2), "=r"(r3) : "r"(addr));
}
__device__ __forceinline__ void mma16816(float* c, const uint32_t* a, uint32_t b0, uint32_t b1) {
    asm volatile("mma.sync.aligned.m16n8k16.row.col.f32.bf16.bf16.f32 "
                 "{%0,%1,%2,%3}, {%4,%5,%6,%7}, {%8,%9}, {%0,%1,%2,%3};"
                 : "+f"(c[0]), "+f"(c[1]), "+f"(c[2]), "+f"(c[3])
                 : "r"(a[0]), "r"(a[1]), "r"(a[2]), "r"(a[3]), "r"(b0), "r"(b1));
}
__device__ __forceinline__ uint32_t pack_bf16(float x, float y) {
    __nv_bfloat162 v = {__float2bfloat16(x), __float2bfloat16(y)};
    return *reinterpret_cast<uint32_t*>(&v);
}

// ---------------- init: zero the step-barrier flags (runs every graph replay) ------
__global__ void init_kernel() {
    if (threadIdx.x < 128) g_flags[threadIdx.x] = 0u;
}

// ---------------- lengths ----------------------------------------------------------
__global__ void lengths_kernel(const float* __restrict__ pads) {
    __shared__ float red[256];
    const int b = blockIdx.x;
    float s = 0.f;
    for (int t = threadIdx.x; t < Tn; t += 256) s += pads[b * Tn + t];
    red[threadIdx.x] = s;
    __syncthreads();
    for (int o = 128; o > 0; o >>= 1) {
        if (threadIdx.x < o) red[threadIdx.x] += red[threadIdx.x + o];
        __syncthreads();
    }
    if (threadIdx.x == 0) g_len[b] = Tn - (int)(red[0] + 0.5f);
}

// ---------------- BN + mask + bf16 hi/lo split -------------------------------------
__global__ void bn_split_kernel(const float* __restrict__ in, const float* __restrict__ pads,
                                const float* __restrict__ scale, const float* __restrict__ bias,
                                const float* __restrict__ mean, const float* __restrict__ var) {
    const int row = blockIdx.x;
    const int d   = threadIdx.x * 4;
    const float keep = 1.0f - pads[row];
    float4 v  = *(const float4*)(in + (size_t)row * Dn + d);
    float4 sc = *(const float4*)(scale + d);
    float4 bi = *(const float4*)(bias + d);
    float4 mu = *(const float4*)(mean + d);
    float4 va = *(const float4*)(var + d);
    float o[4];
    o[0] = ((v.x - mu.x) * ((1.0f + sc.x) * rsqrtf(va.x + EPSC)) + bi.x) * keep;
    o[1] = ((v.y - mu.y) * ((1.0f + sc.y) * rsqrtf(va.y + EPSC)) + bi.y) * keep;
    o[2] = ((v.z - mu.z) * ((1.0f + sc.z) * rsqrtf(va.z + EPSC)) + bi.z) * keep;
    o[3] = ((v.w - mu.w) * ((1.0f + sc.w) * rsqrtf(va.w + EPSC)) + bi.w) * keep;
    __nv_bfloat16 hi[4], lo[4];
#pragma unroll
    for (int q = 0; q < 4; q++) {
        hi[q] = __float2bfloat16(o[q]);
        lo[q] = __float2bfloat16(o[q] - __bfloat162float(hi[q]));
    }
    *(__nv_bfloat162*)(g_ahi + (size_t)row * Dn + d)     = {hi[0], hi[1]};
    *(__nv_bfloat162*)(g_ahi + (size_t)row * Dn + d + 2) = {hi[2], hi[3]};
    *(__nv_bfloat162*)(g_alo + (size_t)row * Dn + d)     = {lo[0], lo[1]};
    *(__nv_bfloat162*)(g_alo + (size_t)row * Dn + d + 2) = {lo[2], lo[3]};
}

// ---------------- W transpose + split + bias concat --------------------------------
__global__ void wprep_kernel(const float* __restrict__ Wxf, const float* __restrict__ Wxb,
                             const float* __restrict__ bf, const float* __restrict__ bb) {
    const int n = blockIdx.x;                 // 0..2047
    const float* W = (n < Gn) ? Wxf : Wxb;
    const int nl = n & (Gn - 1);
    for (int k = threadIdx.x; k < Dn; k += 128) {
        float v = W[(size_t)k * Gn + nl];
        __nv_bfloat16 h = __float2bfloat16(v);
        g_wthi[(size_t)n * Dn + k] = h;
        g_wtlo[(size_t)n * Dn + k] = __float2bfloat16(v - __bfloat162float(h));
    }
    if (threadIdx.x == 0) g_bias2[n] = (n < Gn) ? bf[nl] : bb[nl];
}

// ---------------- mma.sync GEMM with pad-row skip (unchanged, proven) --------------
#define GCHUNKS 24
#define GSTAGE 32768
#define GSMEM  (2 * GSTAGE)

__global__ void __launch_bounds__(256, 2) gemm_mma_kernel() {
    const int n0 = blockIdx.x * 128;
    const int m0 = blockIdx.y * 128;

    {
        const int b  = m0 >> 10;
        const int t0 = m0 & (Tn - 1);
        if (t0 >= g_len[b]) return;
    }

    extern __shared__ __align__(1024) char sm[];
    const uint32_t smb = smem_u32(sm);
    const int tid  = threadIdx.x;
    const int wid  = tid >> 5, lane = tid & 31;
    const int wm   = wid & 3;
    const int wn   = wid >> 2;

    uint32_t sdstA[4];
    int arow[4];
#pragma unroll
    for (int j = 0; j < 4; j++) {
        const int item = tid + j * 256;
        const int row = item >> 3, ci = item & 7;
        arow[j] = row;
        sdstA[j] = row * 128 + ((ci * 16) ^ ((row & 7) << 4));
    }

    auto load_chunk = [&](int c, int s) {
        const int r  = c >> 3;
        const int kp = (c & 7) * 64;
        const __nv_bfloat16* Asrc = (r == 1) ? g_alo : g_ahi;
        const __nv_bfloat16* Bsrc = (r == 2) ? g_wtlo : g_wthi;
        const uint32_t aB = smb + s * GSTAGE;
        const uint32_t bB = aB + 16384;
#pragma unroll
        for (int j = 0; j < 4; j++) {
            const int item = tid + j * 256;
            const int ci = item & 7;
            cp16(aB + sdstA[j], Asrc + (size_t)(m0 + arow[j]) * Dn + kp + ci * 8);
        }
#pragma unroll
        for (int j = 0; j < 4; j++) {
            const int item = tid + j * 256;
            const int ci = item & 7;
            cp16(bB + sdstA[j], Bsrc + (size_t)(n0 + arow[j]) * Dn + kp + ci * 8);
        }
    };

    uint32_t aRel[2], aSx[2];
#pragma unroll
    for (int f = 0; f < 2; f++) {
        const int row = wm * 32 + f * 16 + (lane & 15);
        aRel[f] = row * 128;
        aSx[f]  = (row & 7) << 4;
    }
    uint32_t bRel[4], bSx[4];
#pragma unroll
    for (int q = 0; q < 4; q++) {
        const int row = wn * 64 + q * 16 + (lane & 15);
        bRel[q] = row * 128;
        bSx[q]  = (row & 7) << 4;
    }
    const uint32_t halfOff = (lane >> 4) * 16;

    float acc[2][8][4];
#pragma unroll
    for (int i = 0; i < 2; i++)
#pragma unroll
        for (int j = 0; j < 8; j++)
#pragma unroll
            for (int q = 0; q < 4; q++) acc[i][j][q] = 0.f;

    load_chunk(0, 0); CP_COMMIT();
    load_chunk(1, 1); CP_COMMIT();

    for (int i = 0; i < GCHUNKS; i++) {
        const int buf = i & 1;
        if (i == GCHUNKS - 1) { CP_WAIT0(); } else { CP_WAIT1(); }
        __syncthreads();

        const uint32_t aB = smb + buf * GSTAGE;
        const uint32_t bB = aB + 16384;
#pragma unroll
        for (int k16 = 0; k16 < 4; k16++) {
            const uint32_t kb = k16 * 32 + halfOff;
            uint32_t af[2][4];
#pragma unroll
            for (int f = 0; f < 2; f++)
                ldsm4(af[f][0], af[f][1], af[f][2], af[f][3], aB + aRel[f] + (kb ^ aSx[f]));
#pragma unroll
            for (int q = 0; q < 4; q++) {
                uint32_t r0, r1, r2, r3;
                ldsm4(r0, r1, r2, r3, bB + bRel[q] + (kb ^ bSx[q]));
#pragma unroll
                for (int f = 0; f < 2; f++) {
                    mma16816(acc[f][2 * q + 0], af[f], r0, r2);
                    mma16816(acc[f][2 * q + 1], af[f], r1, r3);
                }
            }
        }
        __syncthreads();
        if (i + 2 < GCHUNKS) { load_chunk(i + 2, buf); CP_COMMIT(); }
    }

#pragma unroll
    for (int f = 0; f < 2; f++) {
        const int r0 = m0 + wm * 32 + f * 16 + (lane >> 2);
#pragma unroll
        for (int nf = 0; nf < 8; nf++) {
            const int col = n0 + wn * 64 + nf * 8 + (lane & 3) * 2;
            const float2 bv = *(const float2*)(g_bias2 + col);
            float2 o0 = {acc[f][nf][0] + bv.x, acc[f][nf][1] + bv.y};
            float2 o1 = {acc[f][nf][2] + bv.x, acc[f][nf][3] + bv.y};
            *(float2*)(g_xg + (size_t)r0 * NTOT + col)       = o0;
            *(float2*)(g_xg + (size_t)(r0 + 8) * NTOT + col) = o1;
        }
    }
}

// ---------------- Recurrence: 2 chains per CTA, 64 CTAs = 2dir x 4bsp x 8hs --------
// CTA hosts chains (dir,bsp) and (dir,bsp+4) — same Wh slice. h tile rows 0-7 =
// chain A, rows 8-15 = chain B (previously zero pad): B-operand ldsm count is
// UNCHANGED; only +3 mma/k16. Barriers/flag-poll/convert/exchange amortized 2x.
#define RSTR    264                       /* bf16 elems per smem row (528 B) */
#define OFF_WHH 0
#define OFF_WHL 67584                     /* 128*528 */
#define OFF_HHH 135168                    /* 16 rows x 528 B */
#define OFF_HHL 143616
#define OFF_G   152064                    /* [16][132] f32 */
#define OFF_C   160512                    /* [512] f32 */
#define OFF_LEN 162560                    /* [16] int */
#define REC_SMEM 162624

__global__ void __launch_bounds__(256, 1) recurrence_kernel(const float* __restrict__ Whf,
                                                            const float* __restrict__ Whb,
                                                            float* __restrict__ out) {
    extern __shared__ __align__(16) char smr[];
    const uint32_t smb = smem_u32(smr);
    __nv_bfloat16* Whh = (__nv_bfloat16*)(smr + OFF_WHH);
    __nv_bfloat16* Whl = (__nv_bfloat16*)(smr + OFF_WHL);
    float* g_sm  = (float*)(smr + OFF_G);     // [16][132]
    float* c_sm  = (float*)(smr + OFF_C);     // [512]  (A: 0..255, B: 256..511)
    int*   len_s = (int*)(smr + OFF_LEN);     // [16]

    const int tid = threadIdx.x;
    const int bx  = blockIdx.x;               // 64 CTAs
    const int dir = bx >> 5;
    const int hs  = bx & 7;
    const int bsp = (bx >> 3) & 3;
    const int j0  = hs * 32;
    const int B0A = bsp * 8;                  // chain A batches
    const int B0B = bsp * 8 + 32;             // chain B batches (bs = bsp+4)
    const float* Wh = dir ? Whb : Whf;

    // ---- init: W slice hi/lo into [c][k] layout (row = local col c = gate*32+jj)
    for (int idx = tid; idx < 32768; idx += 256) {
        const int n = idx & 127, k = idx >> 7;
        const int gate = n >> 5, jj = n & 31;
        const float v = Wh[(size_t)k * Gn + gate * Hn + j0 + jj];
        const __nv_bfloat16 h = __float2bfloat16(v);
        Whh[n * RSTR + k] = h;
        Whl[n * RSTR + k] = __float2bfloat16(v - __bfloat162float(h));
    }
    // zero both 16-row h tiles (t=0 state for both chains)
    for (int idx = tid; idx < (2 * 16 * RSTR * 2) / 4; idx += 256)
        ((uint32_t*)(smr + OFF_HHH))[idx] = 0;
    if (tid < 16) len_s[tid] = g_len[(tid < 8) ? (B0A + tid) : (B0B + tid - 8)];
    c_sm[tid] = 0.f;
    c_sm[256 + tid] = 0.f;
    __syncthreads();

    const int wid = tid >> 5, lane = tid & 31;
    // ldsm base addresses (k-dependent ks*32 added per step)
    const uint32_t aoff = (uint32_t)((wid * 16 + (lane & 15)) * 528 + (lane >> 4) * 16);
    const uint32_t aHH = smb + OFF_WHH + aoff;
    const uint32_t aHL = smb + OFF_WHL + aoff;
    const uint32_t boff = (uint32_t)((lane & 15) * 528 + (lane >> 4) * 16);
    const uint32_t bHH = smb + OFF_HHH + boff;
    const uint32_t bHL = smb + OFF_HHL + boff;

    // epilogue / xg mapping
    const int c_row = wid * 16 + (lane >> 2);            // local col, +8 sibling
    const int bA = (lane & 3) * 2, bB_ = bA + 1;         // two batches within chain
    const int gcol0 = (c_row >> 5) * Hn + j0 + (c_row & 31);
    const int gcol1 = gcol0 + 8;
    const float* xg_dir = g_xg + dir * Gn;
    const float bias0 = g_bias2[dir * Gn + gcol0];
    const float bias1 = g_bias2[dir * Gn + gcol1];
    const int lenAA = len_s[bA],     lenAB = len_s[bB_];       // chain A
    const int lenBA = len_s[8 + bA], lenBB = len_s[8 + bB_];   // chain B

    // conversion mapping: 512 items (16 batches x 32 octets), 2 per thread
    // cell mapping
    const int ub = tid >> 5, uj = tid & 31;
    const int lenUA = len_s[ub], lenUB = len_s[8 + ub];

    unsigned* flagA = &g_flags[dir * 64 + bsp * 8 + hs];
    unsigned* flagB = &g_flags[dir * 64 + (bsp + 4) * 8 + hs];

    for (int t = 0; t < Tn; t++) {
        // ---- xg for this step (both chains): valid rows from memory, pad = bias
        const int rAA = dir ? ((Tn - 1 - t + lenAA) & (Tn - 1)) : t;
        const int rAB = dir ? ((Tn - 1 - t + lenAB) & (Tn - 1)) : t;
        const int rBA = dir ? ((Tn - 1 - t + lenBA) & (Tn - 1)) : t;
        const int rBB = dir ? ((Tn - 1 - t + lenBB) & (Tn - 1)) : t;
        const bool vAA = rAA < lenAA, vAB = rAB < lenAB;
        const bool vBA = rBA < lenBA, vBB = rBB < lenBB;
        const float xA00 = vAA ? __ldg(xg_dir + ((size_t)(B0A + bA)  * Tn + rAA) * NTOT + gcol0) : bias0;
        const float xA01 = vAB ? __ldg(xg_dir + ((size_t)(B0A + bB_) * Tn + rAB) * NTOT + gcol0) : bias0;
        const float xA10 = vAA ? __ldg(xg_dir + ((size_t)(B0A + bA)  * Tn + rAA) * NTOT + gcol1) : bias1;
        const float xA11 = vAB ? __ldg(xg_dir + ((size_t)(B0A + bB_) * Tn + rAB) * NTOT + gcol1) : bias1;
        const float xB00 = vBA ? __ldg(xg_dir + ((size_t)(B0B + bA)  * Tn + rBA) * NTOT + gcol0) : bias0;
        const float xB01 = vBB ? __ldg(xg_dir + ((size_t)(B0B + bB_) * Tn + rBB) * NTOT + gcol0) : bias0;
        const float xB10 = vBA ? __ldg(xg_dir + ((size_t)(B0B + bA)  * Tn + rBA) * NTOT + gcol1) : bias1;
        const float xB11 = vBB ? __ldg(xg_dir + ((size_t)(B0B + bB_) * Tn + rBB) * NTOT + gcol1) : bias1;

        if (t > 0) {
            if (tid < 16) {
                const unsigned* fp = &g_flags[dir * 64 + ((tid < 8) ? bsp : bsp + 4) * 8 + (tid & 7)];
                unsigned v;
                do {
                    asm volatile("ld.acquire.gpu.u32 %0, [%1];" : "=r"(v) : "l"(fp) : "memory");
                } while (v < (unsigned)t);
            }
            __syncthreads();
            // h -> bf16 hi/lo tiles: 512 items, 2 per thread (rows 0-7 = A, 8-15 = B)
            const float* hg = &g_hbuf[(t + 1) & 1][dir][0];
#pragma unroll
            for (int it = 0; it < 2; it++) {
                const int idx = tid + it * 256;
                const int row = idx >> 5, ck = idx & 31;
                const int gb = (row < 8) ? (B0A + row) : (B0B + row - 8);
                const uint32_t cdstH = (uint32_t)(row * 528 + ck * 16);
                const float4 h0 = __ldcg((const float4*)(hg + (size_t)gb * Hn + ck * 8));
                const float4 h1 = __ldcg((const float4*)(hg + (size_t)gb * Hn + ck * 8 + 4));
                const uint32_t p0 = pack_bf16(h0.x, h0.y), p1 = pack_bf16(h0.z, h0.w);
                const uint32_t p2 = pack_bf16(h1.x, h1.y), p3 = pack_bf16(h1.z, h1.w);
                const __nv_bfloat162* hp;
                hp = (const __nv_bfloat162*)&p0;
                const float l0 = h0.x - __bfloat162float(hp->x), l1 = h0.y - __bfloat162float(hp->y);
                hp = (const __nv_bfloat162*)&p1;
                const float l2 = h0.z - __bfloat162float(hp->x), l3 = h0.w - __bfloat162float(hp->y);
                hp = (const __nv_bfloat162*)&p2;
                const float l4 = h1.x - __bfloat162float(hp->x), l5 = h1.y - __bfloat162float(hp->y);
                hp = (const __nv_bfloat162*)&p3;
                const float l6 = h1.z - __bfloat162float(hp->x), l7 = h1.w - __bfloat162float(hp->y);
                *(uint4*)(smr + OFF_HHH + cdstH) = make_uint4(p0, p1, p2, p3);
                *(uint4*)(smr + OFF_HHL + cdstH) =
                    make_uint4(pack_bf16(l0, l1), pack_bf16(l2, l3),
                               pack_bf16(l4, l5), pack_bf16(l6, l7));
            }
            __syncthreads();
        }

        // ---- tensor dot: accA (rows 0-7 of tile), accB (rows 8-15)
        float accA[4] = {0.f, 0.f, 0.f, 0.f};
        float accB[4] = {0.f, 0.f, 0.f, 0.f};
#pragma unroll
        for (int ks = 0; ks < 16; ks++) {
            const uint32_t ko = ks * 32;
            uint32_t awh[4], awl[4], bh0, bh1, bh2, bh3, bl0, bl1, bl2, bl3;
            ldsm4(awh[0], awh[1], awh[2], awh[3], aHH + ko);
            ldsm4(awl[0], awl[1], awl[2], awl[3], aHL + ko);
            ldsm4(bh0, bh1, bh2, bh3, bHH + ko);
            ldsm4(bl0, bl1, bl2, bl3, bHL + ko);
            mma16816(accA, awh, bh0, bh2);
            mma16816(accA, awl, bh0, bh2);
            mma16816(accA, awh, bl0, bl2);
            mma16816(accB, awh, bh1, bh3);
            mma16816(accB, awl, bh1, bh3);
            mma16816(accB, awh, bl1, bl3);
        }

        // ---- epilogue: gates = acc + xg -> g_sm[tilebatch][c]
        g_sm[bA        * 132 + c_row]     = accA[0] + xA00;
        g_sm[bB_       * 132 + c_row]     = accA[1] + xA01;
        g_sm[bA        * 132 + c_row + 8] = accA[2] + xA10;
        g_sm[bB_       * 132 + c_row + 8] = accA[3] + xA11;
        g_sm[(8 + bA)  * 132 + c_row]     = accB[0] + xB00;
        g_sm[(8 + bB_) * 132 + c_row]     = accB[1] + xB01;
        g_sm[(8 + bA)  * 132 + c_row + 8] = accB[2] + xB10;
        g_sm[(8 + bB_) * 132 + c_row + 8] = accB[3] + xB11;
        __syncthreads();

        // ---- LSTM cell update: thread -> (ub, uj) for both chains
        {
            const float* gpA = g_sm + ub * 132 + uj;
            const float ccA = sigf(gpA[32]) * c_sm[tid] + sigf(gpA[0]) * tanhf_(gpA[64]);
            c_sm[tid] = ccA;
            const float hA = sigf(gpA[96]) * tanhf_(ccA);

            const float* gpB = g_sm + (8 + ub) * 132 + uj;
            const float ccB = sigf(gpB[32]) * c_sm[256 + tid] + sigf(gpB[0]) * tanhf_(gpB[64]);
            c_sm[256 + tid] = ccB;
            const float hB = sigf(gpB[96]) * tanhf_(ccB);

            g_hbuf[t & 1][dir][(size_t)(B0A + ub) * Hn + j0 + uj] = hA;
            g_hbuf[t & 1][dir][(size_t)(B0B + ub) * Hn + j0 + uj] = hB;

            const int opA = dir ? ((Tn - 1 - t + lenUA) & (Tn - 1)) : t;
            const int opB = dir ? ((Tn - 1 - t + lenUB) & (Tn - 1)) : t;
            out[((size_t)(B0A + ub) * Tn + opA) * (2 * Hn) + dir * Hn + j0 + uj] = hA;
            out[((size_t)(B0B + ub) * Tn + opB) * (2 * Hn) + dir * Hn + j0 + uj] = hB;
        }
        __syncthreads();
        if (tid == 0) {
            const unsigned nv = (unsigned)(t + 1);
            asm volatile("st.release.gpu.u32 [%0], %1;" ::"l"(flagA), "r"(nv) : "memory");
        }
        if (tid == 1) {
            const unsigned nv = (unsigned)(t + 1);
            asm volatile("st.release.gpu.u32 [%0], %1;" ::"l"(flagB), "r"(nv) : "memory");
        }
    }
}

// ---------------- launch -----------------------------------------------------------
extern "C" void kernel_launch(void* const* d_in, const int* in_sizes, int n_in,
                              void* d_out, int out_size) {
    (void)in_sizes; (void)n_in; (void)out_size;
    const float* inputs   = (const float*)d_in[0];
    const float* pads     = (const float*)d_in[1];
    const float* bn_scale = (const float*)d_in[2];
    const float* bn_bias  = (const float*)d_in[3];
    const float* bn_mean  = (const float*)d_in[4];
    const float* bn_var   = (const float*)d_in[5];
    const float* Wx_f     = (const float*)d_in[6];
    const float* Wh_f     = (const float*)d_in[7];
    const float* b_f      = (const float*)d_in[8];
    const float* Wx_b     = (const float*)d_in[9];
    const float* Wh_b     = (const float*)d_in[10];
    const float* b_b      = (const float*)d_in[11];
    float* out = (float*)d_out;

    static bool inited = false;
    if (!inited) {
        cudaFuncSetAttribute(gemm_mma_kernel,
                             cudaFuncAttributeMaxDynamicSharedMemorySize, GSMEM);
        cudaFuncSetAttribute(recurrence_kernel,
                             cudaFuncAttributeMaxDynamicSharedMemorySize, REC_SMEM);
        inited = true;
    }

    init_kernel<<<1, 128>>>();
    lengths_kernel<<<Bn, 256>>>(pads);
    bn_split_kernel<<<Bn * Tn, 128>>>(inputs, pads, bn_scale, bn_bias, bn_mean, bn_var);
    wprep_kernel<<<NTOT, 128>>>(Wx_f, Wx_b, b_f, b_b);
    gemm_mma_kernel<<<dim3(16, 512), 256, GSMEM>>>();
    recurrence_kernel<<<64, 256, REC_SMEM>>>(Wh_f, Wh_b, out);
}

// round 12
// speedup vs baseline: 1.2702x; 1.2702x over previous
#include <cuda_runtime.h>
#include <cuda_bf16.h>
#include <cstdint>
#include <cstddef>

#define Bn   64
#define Tn   1024
#define Dn   512
#define Hn   256
#define Gn   1024     /* 4*H */
#define NTOT 2048     /* both directions */
#define Mrows (Bn * Tn)
#define EPSC 0.001f

// ---------------- scratch (static device globals; allocation-free) ----------------
__device__ float          g_xg[(size_t)Bn * Tn * NTOT];   // 512 MB  xg for both dirs
__device__ __nv_bfloat16  g_ahi[(size_t)Mrows * Dn];      // 64 MB
__device__ __nv_bfloat16  g_alo[(size_t)Mrows * Dn];      // 64 MB
__device__ __nv_bfloat16  g_wthi[(size_t)NTOT * Dn];      // 2 MB  W^T hi  [n][k]
__device__ __nv_bfloat16  g_wtlo[(size_t)NTOT * Dn];      // 2 MB  W^T lo
__device__ float          g_bias2[NTOT];
__device__ uint32_t       g_hbuf2[2][2][Bn * Hn];         // packed (bf16 hi, bf16 lo)
__device__ int            g_len[Bn];
__device__ unsigned       g_flags[128];                   // [dir*64 + bs*8 + hs]

__device__ __forceinline__ float sigf(float x)  { return 1.0f / (1.0f + __expf(-x)); }
__device__ __forceinline__ float tanhf_(float x){ return 2.0f / (1.0f + __expf(-2.0f * x)) - 1.0f; }

__device__ __forceinline__ uint32_t smem_u32(const void* p) {
    uint32_t a;
    asm("{ .reg .u64 t; cvta.to.shared.u64 t, %1; cvt.u32.u64 %0, t; }" : "=r"(a) : "l"(p));
    return a;
}
__device__ __forceinline__ void cp16(uint32_t dst, const void* src) {
    asm volatile("cp.async.cg.shared.global [%0], [%1], 16;" :: "r"(dst), "l"(src));
}
#define CP_COMMIT() asm volatile("cp.async.commit_group;" ::: "memory")
#define CP_WAIT1()  asm volatile("cp.async.wait_group 1;" ::: "memory")
#define CP_WAIT0()  asm volatile("cp.async.wait_group 0;" ::: "memory")

__device__ __forceinline__ void ldsm4(uint32_t& r0, uint32_t& r1, uint32_t& r2, uint32_t& r3,
                                      uint32_t addr) {
    asm volatile("ldmatrix.sync.aligned.m8n8.x4.shared.b16 {%0,%1,%2,%3}, [%4];"
                 : "=r"(r0), "=r"(r1), "=r"(r2), "=r"(r3) : "r"(addr));
}
__device__ __forceinline__ void mma16816(float* c, const uint32_t* a, uint32_t b0, uint32_t b1) {
    asm volatile("mma.sync.aligned.m16n8k16.row.col.f32.bf16.bf16.f32 "
                 "{%0,%1,%2,%3}, {%4,%5,%6,%7}, {%8,%9}, {%0,%1,%2,%3};"
                 : "+f"(c[0]), "+f"(c[1]), "+f"(c[2]), "+f"(c[3])
                 : "r"(a[0]), "r"(a[1]), "r"(a[2]), "r"(a[3]), "r"(b0), "r"(b1));
}
__device__ __forceinline__ uint32_t pack_bf16(float x, float y) {
    __nv_bfloat162 v = {__float2bfloat16(x), __float2bfloat16(y)};
    return *reinterpret_cast<uint32_t*>(&v);
}

// ---------------- init: zero the step-barrier flags (runs every graph replay) ------
__global__ void init_kernel() {
    if (threadIdx.x < 128) g_flags[threadIdx.x] = 0u;
}

// ---------------- lengths ----------------------------------------------------------
__global__ void lengths_kernel(const float* __restrict__ pads) {
    __shared__ float red[256];
    const int b = blockIdx.x;
    float s = 0.f;
    for (int t = threadIdx.x; t < Tn; t += 256) s += pads[b * Tn + t];
    red[threadIdx.x] = s;
    __syncthreads();
    for (int o = 128; o > 0; o >>= 1) {
        if (threadIdx.x < o) red[threadIdx.x] += red[threadIdx.x + o];
        __syncthreads();
    }
    if (threadIdx.x == 0) g_len[b] = Tn - (int)(red[0] + 0.5f);
}

// ---------------- BN + mask + bf16 hi/lo split -------------------------------------
__global__ void bn_split_kernel(const float* __restrict__ in, const float* __restrict__ pads,
                                const float* __restrict__ scale, const float* __restrict__ bias,
                                const float* __restrict__ mean, const float* __restrict__ var) {
    const int row = blockIdx.x;
    const int d   = threadIdx.x * 4;
    const float keep = 1.0f - pads[row];
    float4 v  = *(const float4*)(in + (size_t)row * Dn + d);
    float4 sc = *(const float4*)(scale + d);
    float4 bi = *(const float4*)(bias + d);
    float4 mu = *(const float4*)(mean + d);
    float4 va = *(const float4*)(var + d);
    float o[4];
    o[0] = ((v.x - mu.x) * ((1.0f + sc.x) * rsqrtf(va.x + EPSC)) + bi.x) * keep;
    o[1] = ((v.y - mu.y) * ((1.0f + sc.y) * rsqrtf(va.y + EPSC)) + bi.y) * keep;
    o[2] = ((v.z - mu.z) * ((1.0f + sc.z) * rsqrtf(va.z + EPSC)) + bi.z) * keep;
    o[3] = ((v.w - mu.w) * ((1.0f + sc.w) * rsqrtf(va.w + EPSC)) + bi.w) * keep;
    __nv_bfloat16 hi[4], lo[4];
#pragma unroll
    for (int q = 0; q < 4; q++) {
        hi[q] = __float2bfloat16(o[q]);
        lo[q] = __float2bfloat16(o[q] - __bfloat162float(hi[q]));
    }
    *(__nv_bfloat162*)(g_ahi + (size_t)row * Dn + d)     = {hi[0], hi[1]};
    *(__nv_bfloat162*)(g_ahi + (size_t)row * Dn + d + 2) = {hi[2], hi[3]};
    *(__nv_bfloat162*)(g_alo + (size_t)row * Dn + d)     = {lo[0], lo[1]};
    *(__nv_bfloat162*)(g_alo + (size_t)row * Dn + d + 2) = {lo[2], lo[3]};
}

// ---------------- W transpose + split + bias concat --------------------------------
__global__ void wprep_kernel(const float* __restrict__ Wxf, const float* __restrict__ Wxb,
                             const float* __restrict__ bf, const float* __restrict__ bb) {
    const int n = blockIdx.x;                 // 0..2047
    const float* W = (n < Gn) ? Wxf : Wxb;
    const int nl = n & (Gn - 1);
    for (int k = threadIdx.x; k < Dn; k += 128) {
        float v = W[(size_t)k * Gn + nl];
        __nv_bfloat16 h = __float2bfloat16(v);
        g_wthi[(size_t)n * Dn + k] = h;
        g_wtlo[(size_t)n * Dn + k] = __float2bfloat16(v - __bfloat162float(h));
    }
    if (threadIdx.x == 0) g_bias2[n] = (n < Gn) ? bf[nl] : bb[nl];
}

// ---------------- mma.sync GEMM with pad-row skip (unchanged, proven) --------------
#define GCHUNKS 24
#define GSTAGE 32768
#define GSMEM  (2 * GSTAGE)

__global__ void __launch_bounds__(256, 2) gemm_mma_kernel() {
    const int n0 = blockIdx.x * 128;
    const int m0 = blockIdx.y * 128;

    {
        const int b  = m0 >> 10;
        const int t0 = m0 & (Tn - 1);
        if (t0 >= g_len[b]) return;
    }

    extern __shared__ __align__(1024) char sm[];
    const uint32_t smb = smem_u32(sm);
    const int tid  = threadIdx.x;
    const int wid  = tid >> 5, lane = tid & 31;
    const int wm   = wid & 3;
    const int wn   = wid >> 2;

    uint32_t sdstA[4];
    int arow[4];
#pragma unroll
    for (int j = 0; j < 4; j++) {
        const int item = tid + j * 256;
        const int row = item >> 3, ci = item & 7;
        arow[j] = row;
        sdstA[j] = row * 128 + ((ci * 16) ^ ((row & 7) << 4));
    }

    auto load_chunk = [&](int c, int s) {
        const int r  = c >> 3;
        const int kp = (c & 7) * 64;
        const __nv_bfloat16* Asrc = (r == 1) ? g_alo : g_ahi;
        const __nv_bfloat16* Bsrc = (r == 2) ? g_wtlo : g_wthi;
        const uint32_t aB = smb + s * GSTAGE;
        const uint32_t bB = aB + 16384;
#pragma unroll
        for (int j = 0; j < 4; j++) {
            const int item = tid + j * 256;
            const int ci = item & 7;
            cp16(aB + sdstA[j], Asrc + (size_t)(m0 + arow[j]) * Dn + kp + ci * 8);
        }
#pragma unroll
        for (int j = 0; j < 4; j++) {
            const int item = tid + j * 256;
            const int ci = item & 7;
            cp16(bB + sdstA[j], Bsrc + (size_t)(n0 + arow[j]) * Dn + kp + ci * 8);
        }
    };

    uint32_t aRel[2], aSx[2];
#pragma unroll
    for (int f = 0; f < 2; f++) {
        const int row = wm * 32 + f * 16 + (lane & 15);
        aRel[f] = row * 128;
        aSx[f]  = (row & 7) << 4;
    }
    uint32_t bRel[4], bSx[4];
#pragma unroll
    for (int q = 0; q < 4; q++) {
        const int row = wn * 64 + q * 16 + (lane & 15);
        bRel[q] = row * 128;
        bSx[q]  = (row & 7) << 4;
    }
    const uint32_t halfOff = (lane >> 4) * 16;

    float acc[2][8][4];
#pragma unroll
    for (int i = 0; i < 2; i++)
#pragma unroll
        for (int j = 0; j < 8; j++)
#pragma unroll
            for (int q = 0; q < 4; q++) acc[i][j][q] = 0.f;

    load_chunk(0, 0); CP_COMMIT();
    load_chunk(1, 1); CP_COMMIT();

    for (int i = 0; i < GCHUNKS; i++) {
        const int buf = i & 1;
        if (i == GCHUNKS - 1) { CP_WAIT0(); } else { CP_WAIT1(); }
        __syncthreads();

        const uint32_t aB = smb + buf * GSTAGE;
        const uint32_t bB = aB + 16384;
#pragma unroll
        for (int k16 = 0; k16 < 4; k16++) {
            const uint32_t kb = k16 * 32 + halfOff;
            uint32_t af[2][4];
#pragma unroll
            for (int f = 0; f < 2; f++)
                ldsm4(af[f][0], af[f][1], af[f][2], af[f][3], aB + aRel[f] + (kb ^ aSx[f]));
#pragma unroll
            for (int q = 0; q < 4; q++) {
                uint32_t r0, r1, r2, r3;
                ldsm4(r0, r1, r2, r3, bB + bRel[q] + (kb ^ bSx[q]));
#pragma unroll
                for (int f = 0; f < 2; f++) {
                    mma16816(acc[f][2 * q + 0], af[f], r0, r2);
                    mma16816(acc[f][2 * q + 1], af[f], r1, r3);
                }
            }
        }
        __syncthreads();
        if (i + 2 < GCHUNKS) { load_chunk(i + 2, buf); CP_COMMIT(); }
    }

#pragma unroll
    for (int f = 0; f < 2; f++) {
        const int r0 = m0 + wm * 32 + f * 16 + (lane >> 2);
#pragma unroll
        for (int nf = 0; nf < 8; nf++) {
            const int col = n0 + wn * 64 + nf * 8 + (lane & 3) * 2;
            const float2 bv = *(const float2*)(g_bias2 + col);
            float2 o0 = {acc[f][nf][0] + bv.x, acc[f][nf][1] + bv.y};
            float2 o1 = {acc[f][nf][2] + bv.x, acc[f][nf][3] + bv.y};
            *(float2*)(g_xg + (size_t)r0 * NTOT + col)       = o0;
            *(float2*)(g_xg + (size_t)(r0 + 8) * NTOT + col) = o1;
        }
    }
}

// ---------------- Recurrence: tensor dot + shfl cell, 128 CTAs = 2dir x 8bs x 8hs --
// W permutation: local col c = jjhi*16 + gate*4 + jjlo (jj = jjhi*4+jjlo). Lane pair
// (l, l^16) holds all 4 gates of one (jj,b): X computes sig(i)tanh(g), shfl to Y,
// Y keeps c-state in registers, stores packed bf16 (hi,lo) h. 2 barriers/step.
#define RSTR    264                       /* bf16 elems per smem row (528 B) */
#define OFF_WHH 0
#define OFF_WHL 67584                     /* 128*528 */
#define OFF_HHH 135168                    /* 16 rows x 528 B */
#define OFF_HHL 143616
#define OFF_LEN 152064                    /* [8] int */
#define REC_SMEM 152128

__global__ void __launch_bounds__(256, 1) recurrence_kernel(const float* __restrict__ Whf,
                                                            const float* __restrict__ Whb,
                                                            float* __restrict__ out) {
    extern __shared__ __align__(16) char smr[];
    const uint32_t smb = smem_u32(smr);
    __nv_bfloat16* Whh = (__nv_bfloat16*)(smr + OFF_WHH);
    __nv_bfloat16* Whl = (__nv_bfloat16*)(smr + OFF_WHL);
    int* len_s = (int*)(smr + OFF_LEN);

    const int tid = threadIdx.x;
    const int bx  = blockIdx.x;
    const int dir = bx >> 6;
    const int hs  = bx & 7;
    const int bs  = (bx >> 3) & 7;
    const int j0  = hs * 32;
    const int b0  = bs * 8;
    const float* Wh = dir ? Whb : Whf;

    // ---- init: W slice hi/lo, gate-interleaved permutation
    for (int idx = tid; idx < 32768; idx += 256) {
        const int n = idx & 127, k = idx >> 7;
        const int jjhi = n >> 4, gate = (n >> 2) & 3, jjlo = n & 3;
        const int jj = jjhi * 4 + jjlo;
        const float v = Wh[(size_t)k * Gn + gate * Hn + j0 + jj];
        const __nv_bfloat16 h = __float2bfloat16(v);
        Whh[n * RSTR + k] = h;
        Whl[n * RSTR + k] = __float2bfloat16(v - __bfloat162float(h));
    }
    // zero both 16-row h tiles (t=0 state; pad rows 8..15 stay zero)
    for (int idx = tid; idx < (2 * 16 * RSTR * 2) / 4; idx += 256)
        ((uint32_t*)(smr + OFF_HHH))[idx] = 0;
    if (tid < 8) len_s[tid] = g_len[b0 + tid];
    __syncthreads();

    const int wid = tid >> 5, lane = tid & 31;
    // ldsm base addresses (k-dependent ks*32 added per step)
    const uint32_t aoff = (uint32_t)((wid * 16 + (lane & 15)) * 528 + (lane >> 4) * 16);
    const uint32_t aHH = smb + OFF_WHH + aoff;
    const uint32_t aHL = smb + OFF_WHL + aoff;
    const uint32_t boff = (uint32_t)((lane & 15) * 528 + (lane >> 4) * 16);
    const uint32_t bHH = smb + OFF_HHH + boff;
    const uint32_t bHL = smb + OFF_HHL + boff;

    // acc/gate mapping: acc[0,1] = col c_row (gate g0) x (bA,bB); acc[2,3] = c_row+8 (gate g0+2)
    const int g0  = lane >> 4;                        // 0 = (i,g) lanes, 1 = (f,o) lanes
    const int jj  = wid * 4 + ((lane >> 2) & 3);
    const int bA  = (lane & 3) * 2, bB_ = bA + 1;
    const int gcol0 = g0 * Hn + j0 + jj;
    const int gcol1 = gcol0 + 2 * Hn;
    const float* xg_dir = g_xg + dir * Gn;
    const float bias0 = g_bias2[dir * Gn + gcol0];
    const float bias1 = g_bias2[dir * Gn + gcol1];
    const int lenA = len_s[bA], lenB = len_s[bB_];

    // conversion mapping: item = (batch cb, k-octet ck)
    const int cb = tid >> 5, ck = tid & 31;
    const uint32_t cdstH = (uint32_t)(cb * 528 + ck * 16);

    unsigned* myflag = &g_flags[dir * 64 + bs * 8 + hs];
    float cA = 0.f, cB = 0.f;                         // cell state (Y lanes only)

    for (int t = 0; t < Tn; t++) {
        // ---- xg for this step: valid rows from memory, pad rows = bias (exact)
        const int rA = dir ? ((Tn - 1 - t + lenA) & (Tn - 1)) : t;
        const int rB = dir ? ((Tn - 1 - t + lenB) & (Tn - 1)) : t;
        const bool vA = rA < lenA, vB = rB < lenB;
        const float x00 = vA ? __ldg(xg_dir + ((size_t)(b0 + bA)  * Tn + rA) * NTOT + gcol0) : bias0;
        const float x01 = vB ? __ldg(xg_dir + ((size_t)(b0 + bB_) * Tn + rB) * NTOT + gcol0) : bias0;
        const float x10 = vA ? __ldg(xg_dir + ((size_t)(b0 + bA)  * Tn + rA) * NTOT + gcol1) : bias1;
        const float x11 = vB ? __ldg(xg_dir + ((size_t)(b0 + bB_) * Tn + rB) * NTOT + gcol1) : bias1;

        if (t > 0) {
            if (tid < 8) {
                const unsigned* fp = &g_flags[dir * 64 + bs * 8 + tid];
                unsigned v;
                do {
                    asm volatile("ld.acquire.gpu.u32 %0, [%1];" : "=r"(v) : "l"(fp) : "memory");
                } while (v < (unsigned)t);
            }
            __syncthreads();
            // packed h -> deinterleave into hi/lo tiles (rows 0..7)
            const uint32_t* hg = &g_hbuf2[(t + 1) & 1][dir][0];
            const uint4 q0 = __ldcg((const uint4*)(hg + (size_t)(b0 + cb) * Hn + ck * 8));
            const uint4 q1 = __ldcg((const uint4*)(hg + (size_t)(b0 + cb) * Hn + ck * 8 + 4));
            uint4 hi, lo;
            hi.x = __byte_perm(q0.x, q0.y, 0x5410); lo.x = __byte_perm(q0.x, q0.y, 0x7632);
            hi.y = __byte_perm(q0.z, q0.w, 0x5410); lo.y = __byte_perm(q0.z, q0.w, 0x7632);
            hi.z = __byte_perm(q1.x, q1.y, 0x5410); lo.z = __byte_perm(q1.x, q1.y, 0x7632);
            hi.w = __byte_perm(q1.z, q1.w, 0x5410); lo.w = __byte_perm(q1.z, q1.w, 0x7632);
            *(uint4*)(smr + OFF_HHH + cdstH) = hi;
            *(uint4*)(smr + OFF_HHL + cdstH) = lo;
            __syncthreads();
        }

        // ---- tensor dot
        float acc[4] = {0.f, 0.f, 0.f, 0.f};
#pragma unroll
        for (int ks = 0; ks < 16; ks++) {
            const uint32_t ko = ks * 32;
            uint32_t awh[4], awl[4], bh0, bh1, bh2, bh3, bl0, bl1, bl2, bl3;
            ldsm4(awh[0], awh[1], awh[2], awh[3], aHH + ko);
            ldsm4(awl[0], awl[1], awl[2], awl[3], aHL + ko);
            ldsm4(bh0, bh1, bh2, bh3, bHH + ko);
            ldsm4(bl0, bl1, bl2, bl3, bHL + ko);
            mma16816(acc, awh, bh0, bh2);
            mma16816(acc, awl, bh0, bh2);
            mma16816(acc, awh, bl0, bl2);
        }

        // ---- gates + shfl cell
        const float v0A = acc[0] + x00;   // X: i-gate, Y: f-gate
        const float v0B = acc[1] + x01;
        const float v2A = acc[2] + x10;   // X: g-gate, Y: o-gate
        const float v2B = acc[3] + x11;
        const float aA = sigf(v0A) * tanhf_(v2A);   // meaningful on X lanes
        const float aB = sigf(v0B) * tanhf_(v2B);
        const float rxA = __shfl_xor_sync(0xffffffffu, aA, 16);
        const float rxB = __shfl_xor_sync(0xffffffffu, aB, 16);
        float hA = 0.f, hB = 0.f;
        if (lane >= 16) {                 // Y lanes: f,o gates + c-state
            cA = sigf(v0A) * cA + rxA;
            cB = sigf(v0B) * cB + rxB;
            hA = sigf(v2A) * tanhf_(cA);
            hB = sigf(v2B) * tanhf_(cB);
            const float hiA = __bfloat162float(__float2bfloat16(hA));
            const float hiB = __bfloat162float(__float2bfloat16(hB));
            g_hbuf2[t & 1][dir][(size_t)(b0 + bA)  * Hn + j0 + jj] = pack_bf16(hA, hA - hiA);
            g_hbuf2[t & 1][dir][(size_t)(b0 + bB_) * Hn + j0 + jj] = pack_bf16(hB, hB - hiB);
        }
        __syncthreads();
        if (tid == 0) {
            const unsigned nv = (unsigned)(t + 1);
            asm volatile("st.release.gpu.u32 [%0], %1;" ::"l"(myflag), "r"(nv) : "memory");
        }
        if (lane >= 16) {                 // out stores after release (overlap peers' wait)
            const int opA = dir ? ((Tn - 1 - t + lenA) & (Tn - 1)) : t;
            const int opB = dir ? ((Tn - 1 - t + lenB) & (Tn - 1)) : t;
            out[((size_t)(b0 + bA)  * Tn + opA) * (2 * Hn) + dir * Hn + j0 + jj] = hA;
            out[((size_t)(b0 + bB_) * Tn + opB) * (2 * Hn) + dir * Hn + j0 + jj] = hB;
        }
    }
}

// ---------------- launch -----------------------------------------------------------
extern "C" void kernel_launch(void* const* d_in, const int* in_sizes, int n_in,
                              void* d_out, int out_size) {
    (void)in_sizes; (void)n_in; (void)out_size;
    const float* inputs   = (const float*)d_in[0];
    const float* pads     = (const float*)d_in[1];
    const float* bn_scale = (const float*)d_in[2];
    const float* bn_bias  = (const float*)d_in[3];
    const float* bn_mean  = (const float*)d_in[4];
    const float* bn_var   = (const float*)d_in[5];
    const float* Wx_f     = (const float*)d_in[6];
    const float* Wh_f     = (const float*)d_in[7];
    const float* b_f      = (const float*)d_in[8];
    const float* Wx_b     = (const float*)d_in[9];
    const float* Wh_b     = (const float*)d_in[10];
    const float* b_b      = (const float*)d_in[11];
    float* out = (float*)d_out;

    static bool inited = false;
    if (!inited) {
        cudaFuncSetAttribute(gemm_mma_kernel,
                             cudaFuncAttributeMaxDynamicSharedMemorySize, GSMEM);
        cudaFuncSetAttribute(recurrence_kernel,
                             cudaFuncAttributeMaxDynamicSharedMemorySize, REC_SMEM);
        inited = true;
    }

    init_kernel<<<1, 128>>>();
    lengths_kernel<<<Bn, 256>>>(pads);
    bn_split_kernel<<<Bn * Tn, 128>>>(inputs, pads, bn_scale, bn_bias, bn_mean, bn_var);
    wprep_kernel<<<NTOT, 128>>>(Wx_f, Wx_b, b_f, b_b);
    gemm_mma_kernel<<<dim3(16, 512), 256, GSMEM>>>();
    recurrence_kernel<<<128, 256, REC_SMEM>>>(Wh_f, Wh_b, out);
}

// round 14
// speedup vs baseline: 1.3796x; 1.0862x over previous
#include <cuda_runtime.h>
#include <cuda_bf16.h>
#include <cstdint>
#include <cstddef>

#define Bn   64
#define Tn   1024
#define Dn   512
#define Hn   256
#define Gn   1024     /* 4*H */
#define NTOT 2048     /* both directions */
#define Mrows (Bn * Tn)
#define EPSC 0.001f

// ---------------- scratch (static device globals; allocation-free) ----------------
__device__ float          g_xg[(size_t)Bn * Tn * NTOT];   // 512 MB  xg for both dirs
__device__ __nv_bfloat16  g_ahi[(size_t)Mrows * Dn];      // 64 MB
__device__ __nv_bfloat16  g_alo[(size_t)Mrows * Dn];      // 64 MB
__device__ __nv_bfloat16  g_wthi[(size_t)NTOT * Dn];      // 2 MB  W^T hi  [n][k]
__device__ __nv_bfloat16  g_wtlo[(size_t)NTOT * Dn];      // 2 MB  W^T lo
__device__ float          g_bias2[NTOT];
__device__ float          g_hbuf[2][2][Bn * Hn];          // [parity][dir][b*H+j]
__device__ int            g_len[Bn];
__device__ unsigned       g_flags[128];                   // [dir*64 + bs*8 + hs]

__device__ __forceinline__ float sigf(float x)  { return 1.0f / (1.0f + __expf(-x)); }
__device__ __forceinline__ float tanhf_(float x){ return 2.0f / (1.0f + __expf(-2.0f * x)) - 1.0f; }

__device__ __forceinline__ uint32_t smem_u32(const void* p) {
    uint32_t a;
    asm("{ .reg .u64 t; cvta.to.shared.u64 t, %1; cvt.u32.u64 %0, t; }" : "=r"(a) : "l"(p));
    return a;
}
__device__ __forceinline__ void cp16(uint32_t dst, const void* src) {
    asm volatile("cp.async.cg.shared.global [%0], [%1], 16;" :: "r"(dst), "l"(src));
}
#define CP_COMMIT() asm volatile("cp.async.commit_group;" ::: "memory")
#define CP_WAIT2()  asm volatile("cp.async.wait_group 2;" ::: "memory")
#define CP_WAIT1()  asm volatile("cp.async.wait_group 1;" ::: "memory")
#define CP_WAIT0()  asm volatile("cp.async.wait_group 0;" ::: "memory")

__device__ __forceinline__ void ldsm4(uint32_t& r0, uint32_t& r1, uint32_t& r2, uint32_t& r3,
                                      uint32_t addr) {
    asm volatile("ldmatrix.sync.aligned.m8n8.x4.shared.b16 {%0,%1,%2,%3}, [%4];"
                 : "=r"(r0), "=r"(r1), "=r"(r2), "=r"(r3) : "r"(addr));
}
__device__ __forceinline__ void mma16816(float* c, const uint32_t* a, uint32_t b0, uint32_t b1) {
    asm volatile("mma.sync.aligned.m16n8k16.row.col.f32.bf16.bf16.f32 "
                 "{%0,%1,%2,%3}, {%4,%5,%6,%7}, {%8,%9}, {%0,%1,%2,%3};"
                 : "+f"(c[0]), "+f"(c[1]), "+f"(c[2]), "+f"(c[3])
                 : "r"(a[0]), "r"(a[1]), "r"(a[2]), "r"(a[3]), "r"(b0), "r"(b1));
}
__device__ __forceinline__ uint32_t pack_bf16(float x, float y) {
    __nv_bfloat162 v = {__float2bfloat16(x), __float2bfloat16(y)};
    return *reinterpret_cast<uint32_t*>(&v);
}

// ---------------- init: zero the step-barrier flags (runs every graph replay) ------
__global__ void init_kernel() {
    if (threadIdx.x < 128) g_flags[threadIdx.x] = 0u;
}

// ---------------- lengths ----------------------------------------------------------
__global__ void lengths_kernel(const float* __restrict__ pads) {
    __shared__ float red[256];
    const int b = blockIdx.x;
    float s = 0.f;
    for (int t = threadIdx.x; t < Tn; t += 256) s += pads[b * Tn + t];
    red[threadIdx.x] = s;
    __syncthreads();
    for (int o = 128; o > 0; o >>= 1) {
        if (threadIdx.x < o) red[threadIdx.x] += red[threadIdx.x + o];
        __syncthreads();
    }
    if (threadIdx.x == 0) g_len[b] = Tn - (int)(red[0] + 0.5f);
}

// ---------------- BN + mask + bf16 hi/lo split -------------------------------------
__global__ void bn_split_kernel(const float* __restrict__ in, const float* __restrict__ pads,
                                const float* __restrict__ scale, const float* __restrict__ bias,
                                const float* __restrict__ mean, const float* __restrict__ var) {
    const int row = blockIdx.x;
    const int d   = threadIdx.x * 4;
    const float keep = 1.0f - pads[row];
    float4 v  = *(const float4*)(in + (size_t)row * Dn + d);
    float4 sc = *(const float4*)(scale + d);
    float4 bi = *(const float4*)(bias + d);
    float4 mu = *(const float4*)(mean + d);
    float4 va = *(const float4*)(var + d);
    float o[4];
    o[0] = ((v.x - mu.x) * ((1.0f + sc.x) * rsqrtf(va.x + EPSC)) + bi.x) * keep;
    o[1] = ((v.y - mu.y) * ((1.0f + sc.y) * rsqrtf(va.y + EPSC)) + bi.y) * keep;
    o[2] = ((v.z - mu.z) * ((1.0f + sc.z) * rsqrtf(va.z + EPSC)) + bi.z) * keep;
    o[3] = ((v.w - mu.w) * ((1.0f + sc.w) * rsqrtf(va.w + EPSC)) + bi.w) * keep;
    __nv_bfloat16 hi[4], lo[4];
#pragma unroll
    for (int q = 0; q < 4; q++) {
        hi[q] = __float2bfloat16(o[q]);
        lo[q] = __float2bfloat16(o[q] - __bfloat162float(hi[q]));
    }
    *(__nv_bfloat162*)(g_ahi + (size_t)row * Dn + d)     = {hi[0], hi[1]};
    *(__nv_bfloat162*)(g_ahi + (size_t)row * Dn + d + 2) = {hi[2], hi[3]};
    *(__nv_bfloat162*)(g_alo + (size_t)row * Dn + d)     = {lo[0], lo[1]};
    *(__nv_bfloat162*)(g_alo + (size_t)row * Dn + d + 2) = {lo[2], lo[3]};
}

// ---------------- W transpose + split + bias concat --------------------------------
__global__ void wprep_kernel(const float* __restrict__ Wxf, const float* __restrict__ Wxb,
                             const float* __restrict__ bf, const float* __restrict__ bb) {
    const int n = blockIdx.x;                 // 0..2047
    const float* W = (n < Gn) ? Wxf : Wxb;
    const int nl = n & (Gn - 1);
    for (int k = threadIdx.x; k < Dn; k += 128) {
        float v = W[(size_t)k * Gn + nl];
        __nv_bfloat16 h = __float2bfloat16(v);
        g_wthi[(size_t)n * Dn + k] = h;
        g_wtlo[(size_t)n * Dn + k] = __float2bfloat16(v - __bfloat162float(h));
    }
    if (threadIdx.x == 0) g_bias2[n] = (n < Gn) ? bf[nl] : bb[nl];
}

// ---------------- mma.sync GEMM, pad-row skip, 3-stage cp.async pipeline -----------
#define GCHUNKS 24
#define GSTAGE 32768
#define GSMEM  (3 * GSTAGE)

__global__ void __launch_bounds__(256, 2) gemm_mma_kernel() {
    const int n0 = blockIdx.x * 128;
    const int m0 = blockIdx.y * 128;

    {   // pad-block skip: entire block is padding -> xg never read, exit
        const int b  = m0 >> 10;
        const int t0 = m0 & (Tn - 1);
        if (t0 >= g_len[b]) return;
    }

    extern __shared__ __align__(1024) char sm[];
    const uint32_t smb = smem_u32(sm);
    const int tid  = threadIdx.x;
    const int wid  = tid >> 5, lane = tid & 31;
    const int wm   = wid & 3;
    const int wn   = wid >> 2;

    uint32_t sdstA[4];
    int arow[4];
#pragma unroll
    for (int j = 0; j < 4; j++) {
        const int item = tid + j * 256;
        const int row = item >> 3, ci = item & 7;
        arow[j] = row;
        sdstA[j] = row * 128 + ((ci * 16) ^ ((row & 7) << 4));
    }

    auto load_chunk = [&](int c, int s) {
        const int r  = c >> 3;
        const int kp = (c & 7) * 64;
        const __nv_bfloat16* Asrc = (r == 1) ? g_alo : g_ahi;
        const __nv_bfloat16* Bsrc = (r == 2) ? g_wtlo : g_wthi;
        const uint32_t aB = smb + s * GSTAGE;
        const uint32_t bB = aB + 16384;
#pragma unroll
        for (int j = 0; j < 4; j++) {
            const int item = tid + j * 256;
            const int ci = item & 7;
            cp16(aB + sdstA[j], Asrc + (size_t)(m0 + arow[j]) * Dn + kp + ci * 8);
        }
#pragma unroll
        for (int j = 0; j < 4; j++) {
            const int item = tid + j * 256;
            const int ci = item & 7;
            cp16(bB + sdstA[j], Bsrc + (size_t)(n0 + arow[j]) * Dn + kp + ci * 8);
        }
    };

    uint32_t aRel[2], aSx[2];
#pragma unroll
    for (int f = 0; f < 2; f++) {
        const int row = wm * 32 + f * 16 + (lane & 15);
        aRel[f] = row * 128;
        aSx[f]  = (row & 7) << 4;
    }
    uint32_t bRel[4], bSx[4];
#pragma unroll
    for (int q = 0; q < 4; q++) {
        const int row = wn * 64 + q * 16 + (lane & 15);
        bRel[q] = row * 128;
        bSx[q]  = (row & 7) << 4;
    }
    const uint32_t halfOff = (lane >> 4) * 16;

    float acc[2][8][4];
#pragma unroll
    for (int i = 0; i < 2; i++)
#pragma unroll
        for (int j = 0; j < 8; j++)
#pragma unroll
            for (int q = 0; q < 4; q++) acc[i][j][q] = 0.f;

    load_chunk(0, 0); CP_COMMIT();
    load_chunk(1, 1); CP_COMMIT();
    load_chunk(2, 2); CP_COMMIT();

    for (int i = 0; i < GCHUNKS; i++) {
        const int buf = i % 3;
        if (i < GCHUNKS - 2)      { CP_WAIT2(); }
        else if (i == GCHUNKS - 2){ CP_WAIT1(); }
        else                      { CP_WAIT0(); }
        __syncthreads();

        const uint32_t aB = smb + buf * GSTAGE;
        const uint32_t bB = aB + 16384;
#pragma unroll
        for (int k16 = 0; k16 < 4; k16++) {
            const uint32_t kb = k16 * 32 + halfOff;
            uint32_t af[2][4];
#pragma unroll
            for (int f = 0; f < 2; f++)
                ldsm4(af[f][0], af[f][1], af[f][2], af[f][3], aB + aRel[f] + (kb ^ aSx[f]));
#pragma unroll
            for (int q = 0; q < 4; q++) {
                uint32_t r0, r1, r2, r3;
                ldsm4(r0, r1, r2, r3, bB + bRel[q] + (kb ^ bSx[q]));
#pragma unroll
                for (int f = 0; f < 2; f++) {
                    mma16816(acc[f][2 * q + 0], af[f], r0, r2);
                    mma16816(acc[f][2 * q + 1], af[f], r1, r3);
                }
            }
        }
        __syncthreads();
        if (i + 3 < GCHUNKS) { load_chunk(i + 3, buf); CP_COMMIT(); }
    }

#pragma unroll
    for (int f = 0; f < 2; f++) {
        const int r0 = m0 + wm * 32 + f * 16 + (lane >> 2);
#pragma unroll
        for (int nf = 0; nf < 8; nf++) {
            const int col = n0 + wn * 64 + nf * 8 + (lane & 3) * 2;
            const float2 bv = *(const float2*)(g_bias2 + col);
            float2 o0 = {acc[f][nf][0] + bv.x, acc[f][nf][1] + bv.y};
            float2 o1 = {acc[f][nf][2] + bv.x, acc[f][nf][3] + bv.y};
            *(float2*)(g_xg + (size_t)r0 * NTOT + col)       = o0;
            *(float2*)(g_xg + (size_t)(r0 + 8) * NTOT + col) = o1;
        }
    }
}

// ---------------- Recurrence (R10-proven, byte-identical): tensor-core dot ---------
// gates[128c][8b] = Wslice[c][k] @ h[b][k]^T via mma m16n8k16 (A=W m=128, B=h n=8).
// Pad rows (rA >= len) read bias from registers instead of g_xg (exact).
#define RSTR    264                       /* bf16 elems per smem row (528 B) */
#define OFF_WHH 0
#define OFF_WHL 67584                     /* 128*528 */
#define OFF_HHH 135168
#define OFF_HHL 143616                    /* +16*528 */
#define OFF_G   152064
#define OFF_C   156288                    /* +8*132*4 */
#define OFF_LEN 157312                    /* +256*4 */
#define REC_SMEM 157376

__global__ void __launch_bounds__(256, 1) recurrence_kernel(const float* __restrict__ Whf,
                                                            const float* __restrict__ Whb,
                                                            float* __restrict__ out) {
    extern __shared__ __align__(16) char smr[];
    const uint32_t smb = smem_u32(smr);
    __nv_bfloat16* Whh = (__nv_bfloat16*)(smr + OFF_WHH);
    __nv_bfloat16* Whl = (__nv_bfloat16*)(smr + OFF_WHL);
    float* g_sm  = (float*)(smr + OFF_G);     // [8][132]
    float* c_sm  = (float*)(smr + OFF_C);     // [256]
    int*   len_s = (int*)(smr + OFF_LEN);     // [8]

    const int tid = threadIdx.x;
    const int bx  = blockIdx.x;
    const int dir = bx >> 6;
    const int hs  = bx & 7;
    const int bs  = (bx >> 3) & 7;
    const int j0  = hs * 32;
    const int b0  = bs * 8;
    const float* Wh = dir ? Whb : Whf;

    // ---- init: W slice hi/lo into [c][k] layout (row = local col c = gate*32+jj)
    for (int idx = tid; idx < 32768; idx += 256) {
        const int n = idx & 127, k = idx >> 7;
        const int gate = n >> 5, jj = n & 31;
        const float v = Wh[(size_t)k * Gn + gate * Hn + j0 + jj];
        const __nv_bfloat16 h = __float2bfloat16(v);
        Whh[n * RSTR + k] = h;
        Whl[n * RSTR + k] = __float2bfloat16(v - __bfloat162float(h));
    }
    // zero both h tiles fully (incl. pad rows 8..15)
    for (int idx = tid; idx < (2 * 16 * RSTR * 2) / 4; idx += 256)
        ((uint32_t*)(smr + OFF_HHH))[idx] = 0;
    if (tid < 8) len_s[tid] = g_len[b0 + tid];
    c_sm[tid] = 0.f;
    __syncthreads();

    const int wid = tid >> 5, lane = tid & 31;
    // ldsm base addresses (k-dependent ks*32 added per step)
    const uint32_t aoff = (uint32_t)((wid * 16 + (lane & 15)) * 528 + (lane >> 4) * 16);
    const uint32_t aHH = smb + OFF_WHH + aoff;
    const uint32_t aHL = smb + OFF_WHL + aoff;
    const uint32_t boff = (uint32_t)((lane & 15) * 528 + (lane >> 4) * 16);
    const uint32_t bHH = smb + OFF_HHH + boff;
    const uint32_t bHL = smb + OFF_HHL + boff;

    // epilogue / xg mapping
    const int c_row = wid * 16 + (lane >> 2);            // local col, +8 sibling
    const int bA = (lane & 3) * 2, bB_ = bA + 1;         // two batches
    const int gcol0 = (c_row >> 5) * Hn + j0 + (c_row & 31);
    const int gcol1 = gcol0 + 8;
    const float* xg_dir = g_xg + dir * Gn;
    const float bias0 = g_bias2[dir * Gn + gcol0];       // pad-row substitute (exact)
    const float bias1 = g_bias2[dir * Gn + gcol1];
    const int lenA = len_s[bA], lenB = len_s[bB_];

    // conversion mapping
    const int cb = tid >> 5, ck = tid & 31;              // batch, k-octet
    const uint32_t cdstH = (uint32_t)(cb * 528 + ck * 16);

    // cell mapping
    const int ub = tid >> 5, uj = tid & 31;

    unsigned* myflag = &g_flags[dir * 64 + bs * 8 + hs];

    for (int t = 0; t < Tn; t++) {
        // ---- xg for this step: valid rows from memory, pad rows = bias (exact)
        const int rA = dir ? ((Tn - 1 - t + lenA) & (Tn - 1)) : t;
        const int rB = dir ? ((Tn - 1 - t + lenB) & (Tn - 1)) : t;
        const bool vA = rA < lenA, vB = rB < lenB;
        const float x00 = vA ? __ldg(xg_dir + ((size_t)(b0 + bA)  * Tn + rA) * NTOT + gcol0) : bias0;
        const float x01 = vB ? __ldg(xg_dir + ((size_t)(b0 + bB_) * Tn + rB) * NTOT + gcol0) : bias0;
        const float x10 = vA ? __ldg(xg_dir + ((size_t)(b0 + bA)  * Tn + rA) * NTOT + gcol1) : bias1;
        const float x11 = vB ? __ldg(xg_dir + ((size_t)(b0 + bB_) * Tn + rB) * NTOT + gcol1) : bias1;

        if (t > 0) {
            if (tid < 8) {
                const unsigned* fp = &g_flags[dir * 64 + bs * 8 + tid];
                unsigned v;
                do {
                    asm volatile("ld.acquire.gpu.u32 %0, [%1];" : "=r"(v) : "l"(fp) : "memory");
                } while (v < (unsigned)t);
            }
            __syncthreads();
            // h -> bf16 hi/lo tiles (rows 0..7)
            const float* hg = &g_hbuf[(t + 1) & 1][dir][0];
            const float4 h0 = __ldcg((const float4*)(hg + (size_t)(b0 + cb) * Hn + ck * 8));
            const float4 h1 = __ldcg((const float4*)(hg + (size_t)(b0 + cb) * Hn + ck * 8 + 4));
            const uint32_t p0 = pack_bf16(h0.x, h0.y), p1 = pack_bf16(h0.z, h0.w);
            const uint32_t p2 = pack_bf16(h1.x, h1.y), p3 = pack_bf16(h1.z, h1.w);
            const __nv_bfloat162* hp;
            hp = (const __nv_bfloat162*)&p0;
            const float l0 = h0.x - __bfloat162float(hp->x), l1 = h0.y - __bfloat162float(hp->y);
            hp = (const __nv_bfloat162*)&p1;
            const float l2 = h0.z - __bfloat162float(hp->x), l3 = h0.w - __bfloat162float(hp->y);
            hp = (const __nv_bfloat162*)&p2;
            const float l4 = h1.x - __bfloat162float(hp->x), l5 = h1.y - __bfloat162float(hp->y);
            hp = (const __nv_bfloat162*)&p3;
            const float l6 = h1.z - __bfloat162float(hp->x), l7 = h1.w - __bfloat162float(hp->y);
            *(uint4*)(smr + OFF_HHH + cdstH) = make_uint4(p0, p1, p2, p3);
            *(uint4*)(smr + OFF_HHL + cdstH) =
                make_uint4(pack_bf16(l0, l1), pack_bf16(l2, l3),
                           pack_bf16(l4, l5), pack_bf16(l6, l7));
            __syncthreads();
        }

        // ---- tensor dot: acc[c_row/(+8)][bA/bB_]
        float acc[4] = {0.f, 0.f, 0.f, 0.f};
#pragma unroll
        for (int ks = 0; ks < 16; ks++) {
            const uint32_t ko = ks * 32;
            uint32_t awh[4], awl[4], bh0, bh1, bh2, bh3, bl0, bl1, bl2, bl3;
            ldsm4(awh[0], awh[1], awh[2], awh[3], aHH + ko);
            ldsm4(awl[0], awl[1], awl[2], awl[3], aHL + ko);
            ldsm4(bh0, bh1, bh2, bh3, bHH + ko);
            ldsm4(bl0, bl1, bl2, bl3, bHL + ko);
            mma16816(acc, awh, bh0, bh2);
            mma16816(acc, awl, bh0, bh2);
            mma16816(acc, awh, bl0, bl2);
        }

        // ---- epilogue: gates = acc + xg -> g_sm[b][c]
        g_sm[bA  * 132 + c_row]     = acc[0] + x00;
        g_sm[bB_ * 132 + c_row]     = acc[1] + x01;
        g_sm[bA  * 132 + c_row + 8] = acc[2] + x10;
        g_sm[bB_ * 132 + c_row + 8] = acc[3] + x11;
        __syncthreads();

        // ---- LSTM cell update: thread -> (ub, uj)
        {
            const float* gp = g_sm + ub * 132 + uj;
            const float gi = gp[0], gf = gp[32], gg2 = gp[64], go = gp[96];
            const float cc = sigf(gf) * c_sm[tid] + sigf(gi) * tanhf_(gg2);
            c_sm[tid] = cc;
            const float hh = sigf(go) * tanhf_(cc);

            g_hbuf[t & 1][dir][(size_t)(b0 + ub) * Hn + j0 + uj] = hh;

            const int opos = dir ? ((Tn - 1 - t + len_s[ub]) & (Tn - 1)) : t;
            out[((size_t)(b0 + ub) * Tn + opos) * (2 * Hn) + dir * Hn + j0 + uj] = hh;
        }
        __syncthreads();
        if (tid == 0) {
            const unsigned nv = (unsigned)(t + 1);
            asm volatile("st.release.gpu.u32 [%0], %1;" ::"l"(myflag), "r"(nv) : "memory");
        }
    }
}

// ---------------- launch -----------------------------------------------------------
extern "C" void kernel_launch(void* const* d_in, const int* in_sizes, int n_in,
                              void* d_out, int out_size) {
    (void)in_sizes; (void)n_in; (void)out_size;
    const float* inputs   = (const float*)d_in[0];
    const float* pads     = (const float*)d_in[1];
    const float* bn_scale = (const float*)d_in[2];
    const float* bn_bias  = (const float*)d_in[3];
    const float* bn_mean  = (const float*)d_in[4];
    const float* bn_var   = (const float*)d_in[5];
    const float* Wx_f     = (const float*)d_in[6];
    const float* Wh_f     = (const float*)d_in[7];
    const float* b_f      = (const float*)d_in[8];
    const float* Wx_b     = (const float*)d_in[9];
    const float* Wh_b     = (const float*)d_in[10];
    const float* b_b      = (const float*)d_in[11];
    float* out = (float*)d_out;

    static bool inited = false;
    if (!inited) {
        cudaFuncSetAttribute(gemm_mma_kernel,
                             cudaFuncAttributeMaxDynamicSharedMemorySize, GSMEM);
        cudaFuncSetAttribute(recurrence_kernel,
                             cudaFuncAttributeMaxDynamicSharedMemorySize, REC_SMEM);
        inited = true;
    }

    init_kernel<<<1, 128>>>();
    lengths_kernel<<<Bn, 256>>>(pads);
    bn_split_kernel<<<Bn * Tn, 128>>>(inputs, pads, bn_scale, bn_bias, bn_mean, bn_var);
    wprep_kernel<<<NTOT, 128>>>(Wx_f, Wx_b, b_f, b_b);
    gemm_mma_kernel<<<dim3(16, 512), 256, GSMEM>>>();
    recurrence_kernel<<<128, 256, REC_SMEM>>>(Wh_f, Wh_b, out);
}